// round 4
// baseline (speedup 1.0000x reference)
#include <cuda_runtime.h>

#define BATCH   4
#define SEQ     2048
#define NH      16
#define DK      64
#define D_MODEL 1024

// Scratch (allocation-free rule: __device__ globals)
__device__ __align__(128) float g_vproj[(size_t)BATCH * SEQ * D_MODEL];
__device__ __align__(128) float g_x[(size_t)BATCH * SEQ * D_MODEL];
// packed mask bits: word w covers mask[w*32 .. w*32+31], bit i = (mask != 0)
__device__ __align__(128) unsigned g_maskbits[(size_t)BATCH * SEQ * (SEQ / 32)];

__device__ __forceinline__ float to_tf32(float x) {
    unsigned u;
    asm("cvt.rna.tf32.f32 %0, %1;" : "=r"(u) : "f"(x));
    return __uint_as_float(u);
}

__device__ __forceinline__ void mma8(float* d, const unsigned* a, unsigned b0, unsigned b1) {
    asm volatile(
        "mma.sync.aligned.m16n8k8.row.col.f32.tf32.tf32.f32 "
        "{%0,%1,%2,%3},{%4,%5,%6,%7},{%8,%9},{%0,%1,%2,%3};\n"
        : "+f"(d[0]), "+f"(d[1]), "+f"(d[2]), "+f"(d[3])
        : "r"(a[0]), "r"(a[1]), "r"(a[2]), "r"(a[3]), "r"(b0), "r"(b1));
}

// ============================================================================
// Pack int32 mask -> bitmask. One warp per 32 consecutive mask elements.
// ============================================================================
__global__ __launch_bounds__(256) void pack_mask(const int* __restrict__ m,
                                                 unsigned* __restrict__ bits,
                                                 int n_words)
{
    int w = blockIdx.x * 8 + (threadIdx.x >> 5);
    int lane = threadIdx.x & 31;
    if (w < n_words) {
        int v = m[(size_t)w * 32 + lane];
        unsigned b = __ballot_sync(0xffffffffu, v != 0);
        if (lane == 0) bits[w] = b;
    }
}

// ============================================================================
// tf32 GEMM: C[M,N] = A[M,K] @ Bw[N,K]^T + bias[N]   (unchanged from R3)
// BM=128, BN=128, BK=32, 256 threads = 8 warps (4m x 2n), warp tile 32x64.
// ============================================================================
__global__ __launch_bounds__(256, 2) void gemm_tf32(
    const float* __restrict__ A, const float* __restrict__ Bw,
    const float* __restrict__ bias, float* __restrict__ C,
    int M, int N, int K)
{
    extern __shared__ float dsm[];

    const int tid  = threadIdx.x;
    const int lane = tid & 31, warp = tid >> 5;
    const int group = lane >> 2, t4 = lane & 3;
    const int wm = warp >> 1, wn = warp & 1;
    const int m0 = blockIdx.y * 128, n0 = blockIdx.x * 128;
    const int lr = tid >> 1, lc = (tid & 1) * 16;

    float acc[2][8][4];
#pragma unroll
    for (int i = 0; i < 2; i++)
#pragma unroll
        for (int j = 0; j < 8; j++)
#pragma unroll
            for (int k = 0; k < 4; k++) acc[i][j][k] = 0.f;

    const float* Ap = A + (size_t)(m0 + lr) * K + lc;
    const float* Bp = Bw + (size_t)(n0 + lr) * K + lc;

    float4 pa[4], pb[4];
#pragma unroll
    for (int j = 0; j < 4; j++) {
        pa[j] = *(const float4*)(Ap + 4 * j);
        pb[j] = *(const float4*)(Bp + 4 * j);
    }
    {
        float* sA0 = dsm;
        float* sB0 = dsm + 9216;
#pragma unroll
        for (int j = 0; j < 4; j++) {
            *(float4*)&sA0[lr * 36 + lc + 4 * j] =
                make_float4(to_tf32(pa[j].x), to_tf32(pa[j].y), to_tf32(pa[j].z), to_tf32(pa[j].w));
            *(float4*)&sB0[lr * 36 + lc + 4 * j] =
                make_float4(to_tf32(pb[j].x), to_tf32(pb[j].y), to_tf32(pb[j].z), to_tf32(pb[j].w));
        }
    }
    __syncthreads();

    const int NC = K / 32;
    for (int c = 0; c < NC; c++) {
        if (c + 1 < NC) {
#pragma unroll
            for (int j = 0; j < 4; j++) {
                pa[j] = *(const float4*)(Ap + (c + 1) * 32 + 4 * j);
                pb[j] = *(const float4*)(Bp + (c + 1) * 32 + 4 * j);
            }
        }
        const float* sAc = dsm + (c & 1) * 4608;
        const float* sBc = dsm + 9216 + (c & 1) * 4608;
#pragma unroll
        for (int kk = 0; kk < 32; kk += 8) {
            unsigned a[2][4];
#pragma unroll
            for (int mf = 0; mf < 2; mf++) {
                int r = wm * 32 + mf * 16 + group;
                a[mf][0] = __float_as_uint(sAc[r * 36 + kk + t4]);
                a[mf][1] = __float_as_uint(sAc[(r + 8) * 36 + kk + t4]);
                a[mf][2] = __float_as_uint(sAc[r * 36 + kk + t4 + 4]);
                a[mf][3] = __float_as_uint(sAc[(r + 8) * 36 + kk + t4 + 4]);
            }
#pragma unroll
            for (int nf = 0; nf < 8; nf++) {
                int n = wn * 64 + nf * 8 + group;
                unsigned b0 = __float_as_uint(sBc[n * 36 + kk + t4]);
                unsigned b1 = __float_as_uint(sBc[n * 36 + kk + t4 + 4]);
#pragma unroll
                for (int mf = 0; mf < 2; mf++) mma8(acc[mf][nf], a[mf], b0, b1);
            }
        }
        if (c + 1 < NC) {
            float* sAn = dsm + ((c + 1) & 1) * 4608;
            float* sBn = dsm + 9216 + ((c + 1) & 1) * 4608;
#pragma unroll
            for (int j = 0; j < 4; j++) {
                *(float4*)&sAn[lr * 36 + lc + 4 * j] =
                    make_float4(to_tf32(pa[j].x), to_tf32(pa[j].y), to_tf32(pa[j].z), to_tf32(pa[j].w));
                *(float4*)&sBn[lr * 36 + lc + 4 * j] =
                    make_float4(to_tf32(pb[j].x), to_tf32(pb[j].y), to_tf32(pb[j].z), to_tf32(pb[j].w));
            }
        }
        __syncthreads();
    }

#pragma unroll
    for (int mf = 0; mf < 2; mf++) {
        int r = m0 + wm * 32 + mf * 16 + group;
#pragma unroll
        for (int nf = 0; nf < 8; nf++) {
            int cc = n0 + wn * 64 + nf * 8 + t4 * 2;
            float b0v = bias[cc], b1v = bias[cc + 1];
            C[(size_t)r * N + cc]           = acc[mf][nf][0] + b0v;
            C[(size_t)r * N + cc + 1]       = acc[mf][nf][1] + b1v;
            C[(size_t)(r + 8) * N + cc]     = acc[mf][nf][2] + b0v;
            C[(size_t)(r + 8) * N + cc + 1] = acc[mf][nf][3] + b1v;
        }
    }
}

// ============================================================================
// Fused softmax + attention mix, 3-deep W prefetch.
// No-max softmax (fp32 logits can't overflow exp; masked entries -> e=0).
// One block = 128 q-rows of one (b,h); k-chunks of 32.
// In-flight invariant at iter c: mma on P stage c%3; convert regs(c+1) ->
// stage (c+1)%3; LDG chunk c+3 -> regset c%3  => 2 W-chunk loads in flight
// per thread (4 per SM) => W stream at DRAM knee.
// smem (floats): P stages @0,4608,9216 (128x36); sV bufs @13824,16128 (32x72);
// rowinv @18432. Total 18560 floats = 74240 B.
// ============================================================================
__global__ __launch_bounds__(256, 2) void mix_softmax(
    const float* __restrict__ W)
{
    extern __shared__ float dsm[];

    const int tid  = threadIdx.x;
    const int lane = tid & 31, warp = tid >> 5;
    const int group = lane >> 2, t4 = lane & 3;
    const int wm = warp >> 1, wn = warp & 1;
    const int bh = blockIdx.y, b = bh >> 4, h = bh & 15;
    const int q0 = blockIdx.x * 128;

    const int rw = tid >> 1, cw = (tid & 1) * 16;   // W loader: 2 thr/row, 16 cols each
    const int rv = tid >> 3, cv = (tid & 7) * 8;    // V loader: 8 thr/row, 8 cols each

    const float*    Wp = W + ((size_t)bh * SEQ + q0 + rw) * SEQ + cw;
    const unsigned* Mb = g_maskbits + ((size_t)b * SEQ + q0 + rw) * (SEQ / 32);
    const float*    Vp = g_vproj + (size_t)b * SEQ * D_MODEL + (size_t)rv * D_MODEL + h * DK + cv;

    float acc[2][4][4];
#pragma unroll
    for (int i = 0; i < 2; i++)
#pragma unroll
        for (int j = 0; j < 4; j++)
#pragma unroll
            for (int k = 0; k < 4; k++) acc[i][j][k] = 0.f;

    float lsum = 0.f;
    float4 wreg[3][4];
    unsigned mreg[3];
    float4 vreg[2];

    // ---- prologue: LDG chunks 0,1,2 into the 3 register sets; V chunk 0 ----
#pragma unroll
    for (int s = 0; s < 3; s++) {
#pragma unroll
        for (int j = 0; j < 4; j++)
            wreg[s][j] = __ldcs((const float4*)(Wp + (size_t)s * 32 + 4 * j));
        mreg[s] = Mb[s];
    }
    vreg[0] = *(const float4*)(Vp);
    vreg[1] = *(const float4*)(Vp + 4);

    // convert chunk 0 -> P stage 0, sV buf 0
    {
        float* sWb = dsm;
        float* sVb = dsm + 13824;
#pragma unroll
        for (int j = 0; j < 4; j++) {
            const float4 wv = wreg[0][j];
            const int base = cw + 4 * j;
            float e0 = ((mreg[0] >> (base + 0)) & 1u) ? __expf(wv.x) : 0.f;
            float e1 = ((mreg[0] >> (base + 1)) & 1u) ? __expf(wv.y) : 0.f;
            float e2 = ((mreg[0] >> (base + 2)) & 1u) ? __expf(wv.z) : 0.f;
            float e3 = ((mreg[0] >> (base + 3)) & 1u) ? __expf(wv.w) : 0.f;
            lsum += (e0 + e1) + (e2 + e3);
            *(float4*)&sWb[rw * 36 + base] =
                make_float4(to_tf32(e0), to_tf32(e1), to_tf32(e2), to_tf32(e3));
        }
        *(float4*)&sVb[rv * 72 + cv] =
            make_float4(to_tf32(vreg[0].x), to_tf32(vreg[0].y), to_tf32(vreg[0].z), to_tf32(vreg[0].w));
        *(float4*)&sVb[rv * 72 + cv + 4] =
            make_float4(to_tf32(vreg[1].x), to_tf32(vreg[1].y), to_tf32(vreg[1].z), to_tf32(vreg[1].w));
    }
    __syncthreads();

    // ---- main loop ----
    for (int c = 0; c < 64; c++) {
        const int set = c % 3;           // regset receiving chunk c+3
        const int nset = (c + 1) % 3;    // regset holding chunk c+1 (to convert)

        if (c + 3 < 64) {
#pragma unroll
            for (int j = 0; j < 4; j++)
                wreg[set][j] = __ldcs((const float4*)(Wp + (size_t)(c + 3) * 32 + 4 * j));
            mreg[set] = Mb[c + 3];
        }
        if (c + 1 < 64) {
            const float* Vn = Vp + (size_t)(c + 1) * 32 * D_MODEL;
            vreg[0] = *(const float4*)(Vn);
            vreg[1] = *(const float4*)(Vn + 4);
        }

        // mma on P stage c%3, sV buf c&1
        {
            const float* sWb = dsm + (c % 3) * 4608;
            const float* sVb = dsm + 13824 + (c & 1) * 2304;
#pragma unroll
            for (int kk = 0; kk < 32; kk += 8) {
                unsigned a[2][4];
#pragma unroll
                for (int mf = 0; mf < 2; mf++) {
                    int r = wm * 32 + mf * 16 + group;
                    a[mf][0] = __float_as_uint(sWb[r * 36 + kk + t4]);
                    a[mf][1] = __float_as_uint(sWb[(r + 8) * 36 + kk + t4]);
                    a[mf][2] = __float_as_uint(sWb[r * 36 + kk + t4 + 4]);
                    a[mf][3] = __float_as_uint(sWb[(r + 8) * 36 + kk + t4 + 4]);
                }
#pragma unroll
                for (int nf = 0; nf < 4; nf++) {
                    int n = wn * 32 + nf * 8 + group;
                    unsigned b0 = __float_as_uint(sVb[(kk + t4) * 72 + n]);
                    unsigned b1 = __float_as_uint(sVb[(kk + t4 + 4) * 72 + n]);
#pragma unroll
                    for (int mf = 0; mf < 2; mf++) mma8(acc[mf][nf], a[mf], b0, b1);
                }
            }
        }

        // convert chunk c+1 -> P stage (c+1)%3, sV buf (c+1)&1
        if (c + 1 < 64) {
            float* sWb = dsm + nset * 4608;
            float* sVb = dsm + 13824 + ((c + 1) & 1) * 2304;
            const unsigned mb = mreg[nset];
#pragma unroll
            for (int j = 0; j < 4; j++) {
                const float4 wv = wreg[nset][j];
                const int base = cw + 4 * j;
                float e0 = ((mb >> (base + 0)) & 1u) ? __expf(wv.x) : 0.f;
                float e1 = ((mb >> (base + 1)) & 1u) ? __expf(wv.y) : 0.f;
                float e2 = ((mb >> (base + 2)) & 1u) ? __expf(wv.z) : 0.f;
                float e3 = ((mb >> (base + 3)) & 1u) ? __expf(wv.w) : 0.f;
                lsum += (e0 + e1) + (e2 + e3);
                *(float4*)&sWb[rw * 36 + base] =
                    make_float4(to_tf32(e0), to_tf32(e1), to_tf32(e2), to_tf32(e3));
            }
            *(float4*)&sVb[rv * 72 + cv] =
                make_float4(to_tf32(vreg[0].x), to_tf32(vreg[0].y), to_tf32(vreg[0].z), to_tf32(vreg[0].w));
            *(float4*)&sVb[rv * 72 + cv + 4] =
                make_float4(to_tf32(vreg[1].x), to_tf32(vreg[1].y), to_tf32(vreg[1].z), to_tf32(vreg[1].w));
        }
        __syncthreads();
    }

    // row sums: 2 threads per row (lane pair), then invert
    {
        float tot = lsum + __shfl_xor_sync(0xffffffffu, lsum, 1);
        if (!(tid & 1)) dsm[18432 + rw] = 1.0f / tot;
    }
    __syncthreads();

    // epilogue: scale by 1/rowsum, write x[b, q, h*64 + d]
    {
        float* Xb = g_x + (size_t)b * SEQ * D_MODEL + h * DK;
#pragma unroll
        for (int mf = 0; mf < 2; mf++) {
            int rr = wm * 32 + mf * 16 + group;
            float s0 = dsm[18432 + rr];
            float s1 = dsm[18432 + rr + 8];
            int qr = q0 + rr;
#pragma unroll
            for (int nf = 0; nf < 4; nf++) {
                int n = wn * 32 + nf * 8 + t4 * 2;
                Xb[(size_t)qr * D_MODEL + n]           = acc[mf][nf][0] * s0;
                Xb[(size_t)qr * D_MODEL + n + 1]       = acc[mf][nf][1] * s0;
                Xb[(size_t)(qr + 8) * D_MODEL + n]     = acc[mf][nf][2] * s1;
                Xb[(size_t)(qr + 8) * D_MODEL + n + 1] = acc[mf][nf][3] * s1;
            }
        }
    }
}

// ============================================================================
// Launch: pack mask -> V-proj GEMM -> fused softmax+mix -> O-proj GEMM
// Inputs: 0 query(unused) 1 key(unused) 2 value 3 weight 4 mask(int32)
//         5 V_w 6 V_b 7 O_w 8 O_b
// ============================================================================
extern "C" void kernel_launch(void* const* d_in, const int* in_sizes, int n_in,
                              void* d_out, int out_size)
{
    const float* value  = (const float*)d_in[2];
    const float* weight = (const float*)d_in[3];
    const int*   mask   = (const int*)d_in[4];
    const float* V_w    = (const float*)d_in[5];
    const float* V_b    = (const float*)d_in[6];
    const float* O_w    = (const float*)d_in[7];
    const float* O_b    = (const float*)d_in[8];
    float* out          = (float*)d_out;

    float *vp, *xp;
    unsigned* mb;
    cudaGetSymbolAddress((void**)&vp, g_vproj);
    cudaGetSymbolAddress((void**)&xp, g_x);
    cudaGetSymbolAddress((void**)&mb, g_maskbits);

    cudaFuncSetAttribute(gemm_tf32, cudaFuncAttributeMaxDynamicSharedMemorySize, 73728);
    cudaFuncSetAttribute(mix_softmax, cudaFuncAttributeMaxDynamicSharedMemorySize, 74240);

    const int n_words = BATCH * SEQ * (SEQ / 32);

    dim3 blk(256);
    dim3 g0((n_words + 7) / 8);
    dim3 g1(D_MODEL / 128, (BATCH * SEQ) / 128);   // (8, 64)
    dim3 g2(SEQ / 128, BATCH * NH);                // (16, 64)

    pack_mask<<<g0, blk>>>(mask, mb, n_words);
    gemm_tf32<<<g1, blk, 73728>>>(value, V_w, V_b, vp, BATCH * SEQ, D_MODEL, D_MODEL);
    mix_softmax<<<g2, blk, 74240>>>(weight);
    gemm_tf32<<<g1, blk, 73728>>>(xp, O_w, O_b, out, BATCH * SEQ, D_MODEL, D_MODEL);
}

// round 5
// speedup vs baseline: 1.3532x; 1.3532x over previous
#include <cuda_runtime.h>

#define BATCH   4
#define SEQ     2048
#define NH      16
#define DK      64
#define D_MODEL 1024

// Scratch (allocation-free rule: __device__ globals)
__device__ __align__(128) float g_vproj[(size_t)BATCH * SEQ * D_MODEL];
__device__ __align__(128) float g_x[(size_t)BATCH * SEQ * D_MODEL];
// packed mask bits: word w covers mask[w*32 .. w*32+31], bit i = (mask != 0)
__device__ __align__(128) unsigned g_maskbits[(size_t)BATCH * SEQ * (SEQ / 32)];

__device__ __forceinline__ float to_tf32(float x) {
    unsigned u;
    asm("cvt.rna.tf32.f32 %0, %1;" : "=r"(u) : "f"(x));
    return __uint_as_float(u);
}

__device__ __forceinline__ void mma8(float* d, const unsigned* a, unsigned b0, unsigned b1) {
    asm volatile(
        "mma.sync.aligned.m16n8k8.row.col.f32.tf32.tf32.f32 "
        "{%0,%1,%2,%3},{%4,%5,%6,%7},{%8,%9},{%0,%1,%2,%3};\n"
        : "+f"(d[0]), "+f"(d[1]), "+f"(d[2]), "+f"(d[3])
        : "r"(a[0]), "r"(a[1]), "r"(a[2]), "r"(a[3]), "r"(b0), "r"(b1));
}

// ============================================================================
// Pack int32 mask -> bitmask. One warp per 32 consecutive mask elements.
// ============================================================================
__global__ __launch_bounds__(256) void pack_mask(const int* __restrict__ m,
                                                 unsigned* __restrict__ bits,
                                                 int n_words)
{
    int w = blockIdx.x * 8 + (threadIdx.x >> 5);
    int lane = threadIdx.x & 31;
    if (w < n_words) {
        int v = m[(size_t)w * 32 + lane];
        unsigned b = __ballot_sync(0xffffffffu, v != 0);
        if (lane == 0) bits[w] = b;
    }
}

// ============================================================================
// tf32 GEMM: C[M,N] = A[M,K] @ Bw[N,K]^T + bias[N]   (unchanged)
// BM=128, BN=128, BK=32, 256 threads = 8 warps (4m x 2n), warp tile 32x64.
// ============================================================================
__global__ __launch_bounds__(256, 2) void gemm_tf32(
    const float* __restrict__ A, const float* __restrict__ Bw,
    const float* __restrict__ bias, float* __restrict__ C,
    int M, int N, int K)
{
    extern __shared__ float dsm[];

    const int tid  = threadIdx.x;
    const int lane = tid & 31, warp = tid >> 5;
    const int group = lane >> 2, t4 = lane & 3;
    const int wm = warp >> 1, wn = warp & 1;
    const int m0 = blockIdx.y * 128, n0 = blockIdx.x * 128;
    const int lr = tid >> 1, lc = (tid & 1) * 16;

    float acc[2][8][4];
#pragma unroll
    for (int i = 0; i < 2; i++)
#pragma unroll
        for (int j = 0; j < 8; j++)
#pragma unroll
            for (int k = 0; k < 4; k++) acc[i][j][k] = 0.f;

    const float* Ap = A + (size_t)(m0 + lr) * K + lc;
    const float* Bp = Bw + (size_t)(n0 + lr) * K + lc;

    float4 pa[4], pb[4];
#pragma unroll
    for (int j = 0; j < 4; j++) {
        pa[j] = *(const float4*)(Ap + 4 * j);
        pb[j] = *(const float4*)(Bp + 4 * j);
    }
    {
        float* sA0 = dsm;
        float* sB0 = dsm + 9216;
#pragma unroll
        for (int j = 0; j < 4; j++) {
            *(float4*)&sA0[lr * 36 + lc + 4 * j] =
                make_float4(to_tf32(pa[j].x), to_tf32(pa[j].y), to_tf32(pa[j].z), to_tf32(pa[j].w));
            *(float4*)&sB0[lr * 36 + lc + 4 * j] =
                make_float4(to_tf32(pb[j].x), to_tf32(pb[j].y), to_tf32(pb[j].z), to_tf32(pb[j].w));
        }
    }
    __syncthreads();

    const int NC = K / 32;
    for (int c = 0; c < NC; c++) {
        if (c + 1 < NC) {
#pragma unroll
            for (int j = 0; j < 4; j++) {
                pa[j] = *(const float4*)(Ap + (c + 1) * 32 + 4 * j);
                pb[j] = *(const float4*)(Bp + (c + 1) * 32 + 4 * j);
            }
        }
        const float* sAc = dsm + (c & 1) * 4608;
        const float* sBc = dsm + 9216 + (c & 1) * 4608;
#pragma unroll
        for (int kk = 0; kk < 32; kk += 8) {
            unsigned a[2][4];
#pragma unroll
            for (int mf = 0; mf < 2; mf++) {
                int r = wm * 32 + mf * 16 + group;
                a[mf][0] = __float_as_uint(sAc[r * 36 + kk + t4]);
                a[mf][1] = __float_as_uint(sAc[(r + 8) * 36 + kk + t4]);
                a[mf][2] = __float_as_uint(sAc[r * 36 + kk + t4 + 4]);
                a[mf][3] = __float_as_uint(sAc[(r + 8) * 36 + kk + t4 + 4]);
            }
#pragma unroll
            for (int nf = 0; nf < 8; nf++) {
                int n = wn * 64 + nf * 8 + group;
                unsigned b0 = __float_as_uint(sBc[n * 36 + kk + t4]);
                unsigned b1 = __float_as_uint(sBc[n * 36 + kk + t4 + 4]);
#pragma unroll
                for (int mf = 0; mf < 2; mf++) mma8(acc[mf][nf], a[mf], b0, b1);
            }
        }
        if (c + 1 < NC) {
            float* sAn = dsm + ((c + 1) & 1) * 4608;
            float* sBn = dsm + 9216 + ((c + 1) & 1) * 4608;
#pragma unroll
            for (int j = 0; j < 4; j++) {
                *(float4*)&sAn[lr * 36 + lc + 4 * j] =
                    make_float4(to_tf32(pa[j].x), to_tf32(pa[j].y), to_tf32(pa[j].z), to_tf32(pa[j].w));
                *(float4*)&sBn[lr * 36 + lc + 4 * j] =
                    make_float4(to_tf32(pb[j].x), to_tf32(pb[j].y), to_tf32(pb[j].z), to_tf32(pb[j].w));
            }
        }
        __syncthreads();
    }

#pragma unroll
    for (int mf = 0; mf < 2; mf++) {
        int r = m0 + wm * 32 + mf * 16 + group;
#pragma unroll
        for (int nf = 0; nf < 8; nf++) {
            int cc = n0 + wn * 64 + nf * 8 + t4 * 2;
            float b0v = bias[cc], b1v = bias[cc + 1];
            C[(size_t)r * N + cc]           = acc[mf][nf][0] + b0v;
            C[(size_t)r * N + cc + 1]       = acc[mf][nf][1] + b1v;
            C[(size_t)(r + 8) * N + cc]     = acc[mf][nf][2] + b0v;
            C[(size_t)(r + 8) * N + cc + 1] = acc[mf][nf][3] + b1v;
        }
    }
}

// ============================================================================
// Fused softmax + attention mix (R3 structure: 2-deep register prefetch, one
// barrier/chunk) + packed mask bits (halves loop DRAM traffic vs R3, and
// drops register pressure -> no spills) + conflict-free sV pitch 72.
// No-max softmax: fp32 logits can't overflow exp; masked entries -> e=0.
// One block = 128 q-rows of one (b,h); k-chunks of 32, 64 chunks.
// 256 threads = 8 warps (4m x 2n), warp tile 32(q) x 32(d).
// smem (floats): sW bufs @0,4608 (128x36); sV bufs @9216,11520 (32x72);
// rowinv @13824 (128). Total 13952 floats = 55808 B.
// ============================================================================
__global__ __launch_bounds__(256, 2) void mix_softmax(
    const float* __restrict__ W)
{
    extern __shared__ float dsm[];

    const int tid  = threadIdx.x;
    const int lane = tid & 31, warp = tid >> 5;
    const int group = lane >> 2, t4 = lane & 3;
    const int wm = warp >> 1, wn = warp & 1;
    const int bh = blockIdx.y, b = bh >> 4, h = bh & 15;
    const int q0 = blockIdx.x * 128;

    const int rw = tid >> 1, cw = (tid & 1) * 16;   // W loader: 2 thr/row, 16 cols each
    const int rv = tid >> 3, cv = (tid & 7) * 8;    // V loader: 8 thr/row, 8 cols each

    const float*    Wp = W + ((size_t)bh * SEQ + q0 + rw) * SEQ + cw;
    const unsigned* Mb = g_maskbits + ((size_t)b * SEQ + q0 + rw) * (SEQ / 32);
    const float*    Vp = g_vproj + (size_t)b * SEQ * D_MODEL + (size_t)rv * D_MODEL + h * DK + cv;

    float acc[2][4][4];
#pragma unroll
    for (int i = 0; i < 2; i++)
#pragma unroll
        for (int j = 0; j < 4; j++)
#pragma unroll
            for (int k = 0; k < 4; k++) acc[i][j][k] = 0.f;

    float lsum = 0.f;
    float4 w[4]; unsigned mb; float4 v[2];

    // prologue: load chunk 0
#pragma unroll
    for (int j = 0; j < 4; j++)
        w[j] = __ldcs((const float4*)(Wp + 4 * j));
    mb = Mb[0];
    v[0] = *(const float4*)(Vp);
    v[1] = *(const float4*)(Vp + 4);

    // exp + store chunk 0 -> buf 0
    {
        float* sWb = dsm;
        float* sVb = dsm + 9216;
#pragma unroll
        for (int j = 0; j < 4; j++) {
            const int base = cw + 4 * j;
            float e0 = ((mb >> (base + 0)) & 1u) ? __expf(w[j].x) : 0.f;
            float e1 = ((mb >> (base + 1)) & 1u) ? __expf(w[j].y) : 0.f;
            float e2 = ((mb >> (base + 2)) & 1u) ? __expf(w[j].z) : 0.f;
            float e3 = ((mb >> (base + 3)) & 1u) ? __expf(w[j].w) : 0.f;
            lsum += (e0 + e1) + (e2 + e3);
            *(float4*)&sWb[rw * 36 + base] =
                make_float4(to_tf32(e0), to_tf32(e1), to_tf32(e2), to_tf32(e3));
        }
        *(float4*)&sVb[rv * 72 + cv] =
            make_float4(to_tf32(v[0].x), to_tf32(v[0].y), to_tf32(v[0].z), to_tf32(v[0].w));
        *(float4*)&sVb[rv * 72 + cv + 4] =
            make_float4(to_tf32(v[1].x), to_tf32(v[1].y), to_tf32(v[1].z), to_tf32(v[1].w));
    }
    __syncthreads();

    for (int c = 0; c < 64; c++) {
        if (c < 63) {
            const float* Wn = Wp + (size_t)(c + 1) * 32;
            const float* Vn = Vp + (size_t)(c + 1) * 32 * D_MODEL;
#pragma unroll
            for (int j = 0; j < 4; j++)
                w[j] = __ldcs((const float4*)(Wn + 4 * j));
            mb = Mb[c + 1];
            v[0] = *(const float4*)(Vn);
            v[1] = *(const float4*)(Vn + 4);
        }

        // mma on buffer c&1
        {
            const float* sWb = dsm + (c & 1) * 4608;
            const float* sVb = dsm + 9216 + (c & 1) * 2304;
#pragma unroll
            for (int kk = 0; kk < 32; kk += 8) {
                unsigned a[2][4];
#pragma unroll
                for (int mf = 0; mf < 2; mf++) {
                    int r = wm * 32 + mf * 16 + group;
                    a[mf][0] = __float_as_uint(sWb[r * 36 + kk + t4]);
                    a[mf][1] = __float_as_uint(sWb[(r + 8) * 36 + kk + t4]);
                    a[mf][2] = __float_as_uint(sWb[r * 36 + kk + t4 + 4]);
                    a[mf][3] = __float_as_uint(sWb[(r + 8) * 36 + kk + t4 + 4]);
                }
#pragma unroll
                for (int nf = 0; nf < 4; nf++) {
                    int n = wn * 32 + nf * 8 + group;
                    unsigned b0 = __float_as_uint(sVb[(kk + t4) * 72 + n]);
                    unsigned b1 = __float_as_uint(sVb[(kk + t4 + 4) * 72 + n]);
#pragma unroll
                    for (int mf = 0; mf < 2; mf++) mma8(acc[mf][nf], a[mf], b0, b1);
                }
            }
        }

        // convert chunk c+1 -> buf (c+1)&1
        if (c < 63) {
            float* sWb = dsm + ((c + 1) & 1) * 4608;
            float* sVb = dsm + 9216 + ((c + 1) & 1) * 2304;
#pragma unroll
            for (int j = 0; j < 4; j++) {
                const int base = cw + 4 * j;
                float e0 = ((mb >> (base + 0)) & 1u) ? __expf(w[j].x) : 0.f;
                float e1 = ((mb >> (base + 1)) & 1u) ? __expf(w[j].y) : 0.f;
                float e2 = ((mb >> (base + 2)) & 1u) ? __expf(w[j].z) : 0.f;
                float e3 = ((mb >> (base + 3)) & 1u) ? __expf(w[j].w) : 0.f;
                lsum += (e0 + e1) + (e2 + e3);
                *(float4*)&sWb[rw * 36 + base] =
                    make_float4(to_tf32(e0), to_tf32(e1), to_tf32(e2), to_tf32(e3));
            }
            *(float4*)&sVb[rv * 72 + cv] =
                make_float4(to_tf32(v[0].x), to_tf32(v[0].y), to_tf32(v[0].z), to_tf32(v[0].w));
            *(float4*)&sVb[rv * 72 + cv + 4] =
                make_float4(to_tf32(v[1].x), to_tf32(v[1].y), to_tf32(v[1].z), to_tf32(v[1].w));
        }
        __syncthreads();
    }

    // row sums: 2 threads per row (lane pair), then invert
    {
        float tot = lsum + __shfl_xor_sync(0xffffffffu, lsum, 1);
        if (!(tid & 1)) dsm[13824 + rw] = 1.0f / tot;
    }
    __syncthreads();

    // epilogue: scale by 1/rowsum, write x[b, q, h*64 + d]
    {
        float* Xb = g_x + (size_t)b * SEQ * D_MODEL + h * DK;
#pragma unroll
        for (int mf = 0; mf < 2; mf++) {
            int rr = wm * 32 + mf * 16 + group;
            float s0 = dsm[13824 + rr];
            float s1 = dsm[13824 + rr + 8];
            int qr = q0 + rr;
#pragma unroll
            for (int nf = 0; nf < 4; nf++) {
                int n = wn * 32 + nf * 8 + t4 * 2;
                Xb[(size_t)qr * D_MODEL + n]           = acc[mf][nf][0] * s0;
                Xb[(size_t)qr * D_MODEL + n + 1]       = acc[mf][nf][1] * s0;
                Xb[(size_t)(qr + 8) * D_MODEL + n]     = acc[mf][nf][2] * s1;
                Xb[(size_t)(qr + 8) * D_MODEL + n + 1] = acc[mf][nf][3] * s1;
            }
        }
    }
}

// ============================================================================
// Launch: pack mask -> V-proj GEMM -> fused softmax+mix -> O-proj GEMM
// Inputs: 0 query(unused) 1 key(unused) 2 value 3 weight 4 mask(int32)
//         5 V_w 6 V_b 7 O_w 8 O_b
// ============================================================================
extern "C" void kernel_launch(void* const* d_in, const int* in_sizes, int n_in,
                              void* d_out, int out_size)
{
    const float* value  = (const float*)d_in[2];
    const float* weight = (const float*)d_in[3];
    const int*   mask   = (const int*)d_in[4];
    const float* V_w    = (const float*)d_in[5];
    const float* V_b    = (const float*)d_in[6];
    const float* O_w    = (const float*)d_in[7];
    const float* O_b    = (const float*)d_in[8];
    float* out          = (float*)d_out;

    float *vp, *xp;
    unsigned* mb;
    cudaGetSymbolAddress((void**)&vp, g_vproj);
    cudaGetSymbolAddress((void**)&xp, g_x);
    cudaGetSymbolAddress((void**)&mb, g_maskbits);

    cudaFuncSetAttribute(gemm_tf32, cudaFuncAttributeMaxDynamicSharedMemorySize, 73728);
    cudaFuncSetAttribute(mix_softmax, cudaFuncAttributeMaxDynamicSharedMemorySize, 55808);

    const int n_words = BATCH * SEQ * (SEQ / 32);

    dim3 blk(256);
    dim3 g0((n_words + 7) / 8);
    dim3 g1(D_MODEL / 128, (BATCH * SEQ) / 128);   // (8, 64)
    dim3 g2(SEQ / 128, BATCH * NH);                // (16, 64)

    pack_mask<<<g0, blk>>>(mask, mb, n_words);
    gemm_tf32<<<g1, blk, 73728>>>(value, V_w, V_b, vp, BATCH * SEQ, D_MODEL, D_MODEL);
    mix_softmax<<<g2, blk, 55808>>>(weight);
    gemm_tf32<<<g1, blk, 73728>>>(xp, O_w, O_b, out, BATCH * SEQ, D_MODEL, D_MODEL);
}